// round 1
// baseline (speedup 1.0000x reference)
#include <cuda_runtime.h>
#include <cuda_bf16.h>
#include <math.h>

// Problem constants
#define L_      32
#define BEAM_   8
#define KV2_    2
#define HEADS_  8
#define SEQ_    1024
#define HDIM_   64
#define VOCAB_  50257
#define HIST_   128
#define TOPK_   8

// Derived
#define CHUNK_FLOATS  (KV2_ * HEADS_ * SEQ_ * HDIM_)      // 1,048,576 floats per (l,beam)
#define CHUNK_F4      (CHUNK_FLOATS / 4)                   // 262,144 float4
#define KV_FLOATS     ((long long)L_ * BEAM_ * CHUNK_FLOATS) // 268,435,456

// Output layout (flattened tuple, float32 values)
#define OFF_KV    0LL
#define OFF_SID   (KV_FLOATS)                 // 8*129 = 1032 ints as floats
#define OFF_PROB  (OFF_SID + 8LL * (HIST_ + 1))
#define OFF_TBI   (OFF_PROB + 8LL)
#define OFF_MAX   (OFF_TBI + 8LL)

// Cross-kernel scratch (no allocations allowed)
__device__ float g_top_val[BEAM_][TOPK_];
__device__ int   g_top_idx[BEAM_][TOPK_];
__device__ float g_lse[BEAM_];
__device__ int   g_beam_index[BEAM_];

__device__ __forceinline__ bool better(float v1, int i1, float v2, int i2) {
    // jax.lax.top_k stable ordering: bigger value first, ties -> lower index first
    return (v1 > v2) || (v1 == v2 && i1 < i2);
}

// ---------------------------------------------------------------------------
// Kernel A: per-beam online logsumexp + top-8 of 50257 logits. 8 blocks.
// ---------------------------------------------------------------------------
__global__ void __launch_bounds__(256) topk_lse_kernel(const float* __restrict__ logits) {
    const int beam = blockIdx.x;
    const int tid  = threadIdx.x;
    const float* row = logits + (long long)beam * VOCAB_;

    float tv[TOPK_];
    int   ti[TOPK_];
#pragma unroll
    for (int i = 0; i < TOPK_; i++) { tv[i] = -INFINITY; ti[i] = 0x7fffffff; }

    float m = -INFINITY, s = 0.0f;

    for (int i = tid; i < VOCAB_; i += 256) {
        float v = __ldg(row + i);
        // online logsumexp
        if (v > m) { s = s * expf(m - v) + 1.0f; m = v; }
        else       { s += expf(v - m); }
        // top-8 register insertion (fully unrolled -> stays in registers)
        if (better(v, i, tv[TOPK_ - 1], ti[TOPK_ - 1])) {
            tv[TOPK_ - 1] = v; ti[TOPK_ - 1] = i;
#pragma unroll
            for (int j = TOPK_ - 1; j > 0; j--) {
                if (better(tv[j], ti[j], tv[j - 1], ti[j - 1])) {
                    float fv = tv[j]; tv[j] = tv[j - 1]; tv[j - 1] = fv;
                    int   fi = ti[j]; ti[j] = ti[j - 1]; ti[j - 1] = fi;
                }
            }
        }
    }

    // ---- LSE block reduction ----
    __shared__ float sm[256], ss[256];
    sm[tid] = m; ss[tid] = s;
    __syncthreads();
    for (int st = 128; st > 0; st >>= 1) {
        if (tid < st) {
            float m2 = sm[tid + st], s2 = ss[tid + st];
            float M  = fmaxf(sm[tid], m2);
            ss[tid]  = ss[tid] * expf(sm[tid] - M) + s2 * expf(m2 - M);
            sm[tid]  = M;
        }
        __syncthreads();
    }
    if (tid == 0) g_lse[beam] = sm[0] + logf(ss[0]);
    __syncthreads();

    // ---- top-8 block merge (pairwise sorted-list merges in shared) ----
    __shared__ float shv[256 * TOPK_];
    __shared__ int   shi[256 * TOPK_];
#pragma unroll
    for (int k = 0; k < TOPK_; k++) { shv[tid * TOPK_ + k] = tv[k]; shi[tid * TOPK_ + k] = ti[k]; }
    __syncthreads();

    for (int st = 128; st > 0; st >>= 1) {
        if (tid < st) {
            float av[TOPK_], bv[TOPK_], rv[TOPK_];
            int   ai[TOPK_], bi[TOPK_], ri[TOPK_];
#pragma unroll
            for (int k = 0; k < TOPK_; k++) {
                av[k] = shv[tid * TOPK_ + k];        ai[k] = shi[tid * TOPK_ + k];
                bv[k] = shv[(tid + st) * TOPK_ + k]; bi[k] = shi[(tid + st) * TOPK_ + k];
            }
            int x = 0, y = 0;
            for (int k = 0; k < TOPK_; k++) {
                bool takeA = (y >= TOPK_) || better(av[x], ai[x], bv[y], bi[y]);
                if (takeA) { rv[k] = av[x]; ri[k] = ai[x]; x++; }
                else       { rv[k] = bv[y]; ri[k] = bi[y]; y++; }
            }
#pragma unroll
            for (int k = 0; k < TOPK_; k++) { shv[tid * TOPK_ + k] = rv[k]; shi[tid * TOPK_ + k] = ri[k]; }
        }
        __syncthreads();
    }

    if (tid < TOPK_) {
        g_top_val[beam][tid] = shv[tid];
        g_top_idx[beam][tid] = shi[tid];
    }
}

// ---------------------------------------------------------------------------
// Kernel B: top-8 of the 64 combined probs, write small outputs + beam_index.
// ---------------------------------------------------------------------------
__global__ void __launch_bounds__(128) select_kernel(const int* __restrict__ save_id,
                                                     const float* __restrict__ prev,
                                                     float* __restrict__ out) {
    __shared__ float cur[BEAM_ * TOPK_];
    __shared__ int   s_beam[BEAM_], s_tok[BEAM_];
    __shared__ float s_prob[BEAM_];
    const int t = threadIdx.x;

    if (t < BEAM_ * TOPK_) {
        int b = t >> 3, k = t & 7;
        cur[t] = g_top_val[b][k] - g_lse[b] + __ldg(prev + b);
    }
    __syncthreads();

    if (t == 0) {
        bool taken[BEAM_ * TOPK_];
        for (int j = 0; j < BEAM_ * TOPK_; j++) taken[j] = false;
        for (int r = 0; r < BEAM_; r++) {
            int best = -1; float bv = -INFINITY;
            for (int j = 0; j < BEAM_ * TOPK_; j++) {
                if (!taken[j] && cur[j] > bv) { bv = cur[j]; best = j; } // ascending scan => ties take lower index
            }
            taken[best] = true;
            int b = best >> 3, k = best & 7;
            s_beam[r] = b;
            s_tok[r]  = g_top_idx[b][k];
            s_prob[r] = bv;
            g_beam_index[r] = b;
        }
    }
    __syncthreads();

    // new_save_id: (8, 129) -> gathered rows + appended token, written as float values
    for (int i = t; i < BEAM_ * (HIST_ + 1); i += blockDim.x) {
        int b = i / (HIST_ + 1), c = i % (HIST_ + 1);
        int v = (c < HIST_) ? __ldg(save_id + s_beam[b] * HIST_ + c) : s_tok[b];
        out[OFF_SID + i] = (float)v;
    }
    if (t < BEAM_) {
        out[OFF_PROB + t] = s_prob[t];
        out[OFF_TBI  + t] = (float)s_tok[t];
    }
    if (t == 0) out[OFF_MAX] = (float)s_tok[0];
}

// ---------------------------------------------------------------------------
// Kernel C: the 1 GiB beam-permuted KV copy. This is the roofline kernel.
// grid = (CHUNK_F4 / (256*8), L_*BEAM_) ; block = 256 ; 8 x float4 per thread.
// Duplicate-source beams are adjacent in blockIdx.y order -> L2 reuse.
// ---------------------------------------------------------------------------
#define GITER 8
__global__ void __launch_bounds__(256) gather_kv_kernel(const float4* __restrict__ src,
                                                        float4* __restrict__ dst) {
    const int lb = blockIdx.y;           // 0..255 : destination (l, beam)
    const int b  = lb & (BEAM_ - 1);
    const int l  = lb >> 3;
    const int src_lb = l * BEAM_ + g_beam_index[b];

    const float4* __restrict__ s = src + (size_t)src_lb * CHUNK_F4;
    float4* __restrict__       d = dst + (size_t)lb     * CHUNK_F4;

    const int base = blockIdx.x * (256 * GITER) + threadIdx.x;
#pragma unroll
    for (int i = 0; i < GITER; i++) {
        d[base + i * 256] = s[base + i * 256];
    }
}

// ---------------------------------------------------------------------------
extern "C" void kernel_launch(void* const* d_in, const int* in_sizes, int n_in,
                              void* d_out, int out_size) {
    const float* kv      = (const float*)d_in[0];
    const float* logits  = (const float*)d_in[1];
    const int*   save_id = (const int*)  d_in[2];
    const float* prev    = (const float*)d_in[3];
    float*       out     = (float*)d_out;

    topk_lse_kernel<<<BEAM_, 256>>>(logits);
    select_kernel<<<1, 128>>>(save_id, prev, out);

    dim3 grid(CHUNK_F4 / (256 * GITER), L_ * BEAM_);
    gather_kv_kernel<<<grid, 256>>>((const float4*)kv, (float4*)(out + OFF_KV));
}

// round 2
// speedup vs baseline: 1.5490x; 1.5490x over previous
#include <cuda_runtime.h>
#include <cuda_bf16.h>
#include <math.h>

// Problem constants
#define L_      32
#define BEAM_   8
#define KV2_    2
#define HEADS_  8
#define SEQ_    1024
#define HDIM_   64
#define VOCAB_  50257
#define HIST_   128
#define TOPK_   8

// Phase-1 split of the vocab scan
#define NSPLIT  32
#define SPLEN   1571               // ceil(50257/32); 32*1571 = 50272 >= 50257

// Derived
#define CHUNK_FLOATS  (KV2_ * HEADS_ * SEQ_ * HDIM_)        // 1,048,576 floats per (l,beam)
#define CHUNK_F4      (CHUNK_FLOATS / 4)                    // 262,144 float4
#define KV_FLOATS     ((long long)L_ * BEAM_ * CHUNK_FLOATS)

// Output layout (flattened tuple, float32 values)
#define OFF_KV    0LL
#define OFF_SID   (KV_FLOATS)
#define OFF_PROB  (OFF_SID + 8LL * (HIST_ + 1))
#define OFF_TBI   (OFF_PROB + 8LL)
#define OFF_MAX   (OFF_TBI + 8LL)

// Cross-kernel scratch (__device__ globals: no allocations allowed)
__device__ float g_part_val[BEAM_][NSPLIT][TOPK_];
__device__ int   g_part_idx[BEAM_][NSPLIT][TOPK_];
__device__ float g_part_m[BEAM_][NSPLIT];
__device__ float g_part_s[BEAM_][NSPLIT];
__device__ float g_top_val[BEAM_][TOPK_];
__device__ int   g_top_idx[BEAM_][TOPK_];
__device__ float g_lse[BEAM_];
__device__ int   g_beam_index[BEAM_];

__device__ __forceinline__ bool better(float v1, int i1, float v2, int i2) {
    // jax.lax.top_k stable ordering: bigger value first, ties -> lower index first
    return (v1 > v2) || (v1 == v2 && i1 < i2);
}

// ---------------------------------------------------------------------------
// Phase 1: 256 blocks (8 beams x 32 splits). Each block: partial top-8 + (m,s).
// Each thread handles <= 7 logits, all resident in registers.
// ---------------------------------------------------------------------------
__global__ void __launch_bounds__(256) topk_phase1(const float* __restrict__ logits) {
    const int beam  = blockIdx.x >> 5;
    const int split = blockIdx.x & (NSPLIT - 1);
    const int tid   = threadIdx.x;
    const int start = split * SPLEN;
    const int end   = min(start + SPLEN, VOCAB_);
    const float* row = logits + (long long)beam * VOCAB_;

    // Load my elements into registers (<= 7)
    float ev[7];
    int   ei[7];
    int   cnt = 0;
#pragma unroll
    for (int k = 0; k < 7; k++) {
        int i = start + tid + k * 256;
        if (i < end) { ev[cnt] = __ldg(row + i); ei[cnt] = i; cnt++; }
    }

    // Local max then sum of exp (no serial online-LSE dependency)
    float m = -INFINITY;
#pragma unroll
    for (int k = 0; k < 7; k++) if (k < cnt) m = fmaxf(m, ev[k]);
    float s = 0.0f;
#pragma unroll
    for (int k = 0; k < 7; k++) if (k < cnt) s += expf(ev[k] - m);

    // Thread-local sorted top-8 (insertion)
    float tv[TOPK_];
    int   ti[TOPK_];
#pragma unroll
    for (int i = 0; i < TOPK_; i++) { tv[i] = -INFINITY; ti[i] = 0x7fffffff; }
#pragma unroll
    for (int k = 0; k < 7; k++) {
        if (k < cnt) {
            float v = ev[k]; int idx = ei[k];
            if (better(v, idx, tv[TOPK_ - 1], ti[TOPK_ - 1])) {
                tv[TOPK_ - 1] = v; ti[TOPK_ - 1] = idx;
#pragma unroll
                for (int j = TOPK_ - 1; j > 0; j--) {
                    if (better(tv[j], ti[j], tv[j - 1], ti[j - 1])) {
                        float fv = tv[j]; tv[j] = tv[j - 1]; tv[j - 1] = fv;
                        int   fi = ti[j]; ti[j] = ti[j - 1]; ti[j - 1] = fi;
                    }
                }
            }
        }
    }

    // ---- (m,s) block reduction ----
    __shared__ float sm[256], ss[256];
    sm[tid] = m; ss[tid] = s;
    __syncthreads();
    for (int st = 128; st > 0; st >>= 1) {
        if (tid < st) {
            float m2 = sm[tid + st], s2 = ss[tid + st];
            float M  = fmaxf(sm[tid], m2);
            ss[tid]  = ss[tid] * expf(sm[tid] - M) + s2 * expf(m2 - M);
            sm[tid]  = M;
        }
        __syncthreads();
    }
    if (tid == 0) { g_part_m[beam][split] = sm[0]; g_part_s[beam][split] = ss[0]; }
    __syncthreads();

    // ---- top-8 block merge tree ----
    __shared__ float shv[256 * TOPK_];
    __shared__ int   shi[256 * TOPK_];
#pragma unroll
    for (int k = 0; k < TOPK_; k++) { shv[tid * TOPK_ + k] = tv[k]; shi[tid * TOPK_ + k] = ti[k]; }
    __syncthreads();

    for (int st = 128; st > 0; st >>= 1) {
        if (tid < st) {
            float av[TOPK_], bv[TOPK_], rv[TOPK_];
            int   ai[TOPK_], bi[TOPK_], ri[TOPK_];
#pragma unroll
            for (int k = 0; k < TOPK_; k++) {
                av[k] = shv[tid * TOPK_ + k];        ai[k] = shi[tid * TOPK_ + k];
                bv[k] = shv[(tid + st) * TOPK_ + k]; bi[k] = shi[(tid + st) * TOPK_ + k];
            }
            int x = 0, y = 0;
#pragma unroll
            for (int k = 0; k < TOPK_; k++) {
                bool takeA = (y >= TOPK_) || (x < TOPK_ && better(av[x], ai[x], bv[y], bi[y]));
                if (takeA) { rv[k] = av[x]; ri[k] = ai[x]; x++; }
                else       { rv[k] = bv[y]; ri[k] = bi[y]; y++; }
            }
#pragma unroll
            for (int k = 0; k < TOPK_; k++) { shv[tid * TOPK_ + k] = rv[k]; shi[tid * TOPK_ + k] = ri[k]; }
        }
        __syncthreads();
    }

    if (tid < TOPK_) {
        g_part_val[beam][split][tid] = shv[tid];
        g_part_idx[beam][split][tid] = shi[tid];
    }
}

// ---------------------------------------------------------------------------
// Phase 2: 8 blocks (one per beam), 32 threads. Merge 32 partial lists + LSE.
// ---------------------------------------------------------------------------
__global__ void __launch_bounds__(32) topk_phase2() {
    const int beam = blockIdx.x;
    const int tid  = threadIdx.x;

    __shared__ float shv[NSPLIT * TOPK_];
    __shared__ int   shi[NSPLIT * TOPK_];
    __shared__ float sm[NSPLIT], ss[NSPLIT];

#pragma unroll
    for (int k = 0; k < TOPK_; k++) {
        shv[tid * TOPK_ + k] = g_part_val[beam][tid][k];
        shi[tid * TOPK_ + k] = g_part_idx[beam][tid][k];
    }
    sm[tid] = g_part_m[beam][tid];
    ss[tid] = g_part_s[beam][tid];
    __syncthreads();

    for (int st = 16; st > 0; st >>= 1) {
        if (tid < st) {
            // LSE pair merge
            float m2 = sm[tid + st], s2 = ss[tid + st];
            float M  = fmaxf(sm[tid], m2);
            ss[tid]  = ss[tid] * expf(sm[tid] - M) + s2 * expf(m2 - M);
            sm[tid]  = M;
            // top-8 list merge
            float av[TOPK_], bv[TOPK_], rv[TOPK_];
            int   ai[TOPK_], bi[TOPK_], ri[TOPK_];
#pragma unroll
            for (int k = 0; k < TOPK_; k++) {
                av[k] = shv[tid * TOPK_ + k];        ai[k] = shi[tid * TOPK_ + k];
                bv[k] = shv[(tid + st) * TOPK_ + k]; bi[k] = shi[(tid + st) * TOPK_ + k];
            }
            int x = 0, y = 0;
#pragma unroll
            for (int k = 0; k < TOPK_; k++) {
                bool takeA = (y >= TOPK_) || (x < TOPK_ && better(av[x], ai[x], bv[y], bi[y]));
                if (takeA) { rv[k] = av[x]; ri[k] = ai[x]; x++; }
                else       { rv[k] = bv[y]; ri[k] = bi[y]; y++; }
            }
#pragma unroll
            for (int k = 0; k < TOPK_; k++) { shv[tid * TOPK_ + k] = rv[k]; shi[tid * TOPK_ + k] = ri[k]; }
        }
        __syncthreads();
    }

    if (tid < TOPK_) {
        g_top_val[beam][tid] = shv[tid];
        g_top_idx[beam][tid] = shi[tid];
    }
    if (tid == 0) g_lse[beam] = sm[0] + logf(ss[0]);
}

// ---------------------------------------------------------------------------
// Select: top-8 of the 64 combined probs, write small outputs + beam_index.
// ---------------------------------------------------------------------------
__global__ void __launch_bounds__(128) select_kernel(const int* __restrict__ save_id,
                                                     const float* __restrict__ prev,
                                                     float* __restrict__ out) {
    __shared__ float cur[BEAM_ * TOPK_];
    __shared__ int   s_beam[BEAM_], s_tok[BEAM_];
    __shared__ float s_prob[BEAM_];
    const int t = threadIdx.x;

    if (t < BEAM_ * TOPK_) {
        int b = t >> 3, k = t & 7;
        cur[t] = g_top_val[b][k] - g_lse[b] + __ldg(prev + b);
    }
    __syncthreads();

    if (t == 0) {
        bool taken[BEAM_ * TOPK_];
        for (int j = 0; j < BEAM_ * TOPK_; j++) taken[j] = false;
        for (int r = 0; r < BEAM_; r++) {
            int best = -1; float bv = -INFINITY;
            for (int j = 0; j < BEAM_ * TOPK_; j++) {
                if (!taken[j] && cur[j] > bv) { bv = cur[j]; best = j; } // ties -> lower index
            }
            taken[best] = true;
            int b = best >> 3, k = best & 7;
            s_beam[r] = b;
            s_tok[r]  = g_top_idx[b][k];
            s_prob[r] = bv;
            g_beam_index[r] = b;
        }
    }
    __syncthreads();

    for (int i = t; i < BEAM_ * (HIST_ + 1); i += blockDim.x) {
        int b = i / (HIST_ + 1), c = i % (HIST_ + 1);
        int v = (c < HIST_) ? __ldg(save_id + s_beam[b] * HIST_ + c) : s_tok[b];
        out[OFF_SID + i] = (float)v;
    }
    if (t < BEAM_) {
        out[OFF_PROB + t] = s_prob[t];
        out[OFF_TBI  + t] = (float)s_tok[t];
    }
    if (t == 0) out[OFF_MAX] = (float)s_tok[0];
}

// ---------------------------------------------------------------------------
// Gather: the 1 GiB beam-permuted KV copy (roofline kernel, unchanged).
// ---------------------------------------------------------------------------
#define GITER 8
__global__ void __launch_bounds__(256) gather_kv_kernel(const float4* __restrict__ src,
                                                        float4* __restrict__ dst) {
    const int lb = blockIdx.y;           // destination (l, beam)
    const int b  = lb & (BEAM_ - 1);
    const int l  = lb >> 3;
    const int src_lb = l * BEAM_ + g_beam_index[b];

    const float4* __restrict__ s = src + (size_t)src_lb * CHUNK_F4;
    float4* __restrict__       d = dst + (size_t)lb     * CHUNK_F4;

    const int base = blockIdx.x * (256 * GITER) + threadIdx.x;
#pragma unroll
    for (int i = 0; i < GITER; i++) {
        d[base + i * 256] = s[base + i * 256];
    }
}

// ---------------------------------------------------------------------------
extern "C" void kernel_launch(void* const* d_in, const int* in_sizes, int n_in,
                              void* d_out, int out_size) {
    const float* kv      = (const float*)d_in[0];
    const float* logits  = (const float*)d_in[1];
    const int*   save_id = (const int*)  d_in[2];
    const float* prev    = (const float*)d_in[3];
    float*       out     = (float*)d_out;

    topk_phase1<<<BEAM_ * NSPLIT, 256>>>(logits);
    topk_phase2<<<BEAM_, 32>>>();
    select_kernel<<<1, 128>>>(save_id, prev, out);

    dim3 grid(CHUNK_F4 / (256 * GITER), L_ * BEAM_);
    gather_kv_kernel<<<grid, 256>>>((const float4*)kv, (float4*)(out + OFF_KV));
}